// round 14
// baseline (speedup 1.0000x reference)
#include <cuda_runtime.h>
#include <cstdint>

// Problem constants (from reference_code)
#define DD    14
#define KK    2
#define BB    512
#define FF    512
#define NT    512
#define NF    1024
#define CELLS (BB * FF)          // 262144 (b,f) cells
#define PIX   (DD * DD)          // 196 pixels per cell
#define CPB   32                 // cells per block
#define THREADS 128
#define STRIDE 34                // float2 per cell: ex[pos 0..15] ey[16..31] pad[2]
                                 // = 17 x 16B chunks; 17 odd -> conflict-free 128b ops

__device__ __forceinline__ float ex2(float a) {
    float r;
    asm("ex2.approx.ftz.f32 %0, %1;" : "=f"(r) : "f"(a));
    return r;
}

// Block handles 32 consecutive (b,f) cells.
//
// ex table is 4x4-TRANSPOSED: entry for row lives at pos (row%4)*4 + row/4.
// A phase-2 lane (row-subgroup ri) finds its four rows (ri,4+ri,8+ri,12+ri)
// at positions 4ri..4ri+3 = 32 contiguous bytes -> TWO LDS.128 before the
// round loop; rounds are pure FMA + STG (no in-loop smem reads, no selects:
// unrolled compile-time component access). ey table stays linear.
//
// Phase 1 (ALL 128 threads, warp-uniform roles): thread (axis, hf, cell):
//   axis==0 (ex): TWO step-4 recurrences (runs start rows 2hf, 2hf+1;
//     2nd difference of a(r0+4m) is -32*s2) -> emits positions 8hf..8hf+7
//     in order, pairwise conflict-free STS.128. Rows 14/15 land at positions
//     11/15 as computed-garbage (finite; masked at store).
//   axis==1 (ey): step-1 recurrence as before, positions 16+8hf..,
//     last pair (rows 14,15) masked.
// Phase 2 (4 warps x 8 cells): lane l -> (ri=l/7, jp=l%7); lanes 28..31
//   duplicate lane 0 (same value+address -> merged store, no predicate).
//   r=0..2 stores unconditional; r=3 predicated (ri<2). Streaming STG.64.
__global__ __launch_bounds__(THREADS, 15) void gaussian_spot_kernel(
    const float* __restrict__ height,      // [K,B,F]
    const float* __restrict__ width,       // [K,B,F]
    const float* __restrict__ x,           // [K,B,F]
    const float* __restrict__ y,           // [K,B,F]
    const float* __restrict__ background,  // [B,F]
    const float* __restrict__ target_locs, // [NT,NF,2]
    const int*   __restrict__ n_idx,       // [B,1]
    const int*   __restrict__ f_arr,       // [F]
    float*       __restrict__ out)         // [1,B,F,D,D]
{
    __shared__ __align__(16) float2 tab[CPB * STRIDE];   // 8704 B
    __shared__ float bgs[CPB];

    const int t = threadIdx.x;
    const int blockbase = blockIdx.x * CPB;

    // ---------------- Phase 1: build tables (all 128 threads) --------------
    {
        const int lc   = t & (CPB - 1);   // 0..31
        const int sub  = t >> 5;          // 0..3 (= warp id: no divergence)
        const int axis = sub & 1;         // 0 = x/i-axis (ex), 1 = y/j-axis (ey)
        const int hf   = sub >> 1;        // segment half
        const int cell = blockbase + lc;
        const int b = cell >> 9;          // / FF
        const int f = cell & (FF - 1);

        const int n  = n_idx[b];          // broadcast within block
        const int fi = f_arr[f];          // coalesced
        const float cloc = target_locs[((size_t)n * NF + (size_t)fi) * 2 + axis];
        if (sub == 0) bgs[lc] = background[cell];   // coalesced, once

        float c[KK], s2[KK], lp2[KK];
#pragma unroll
        for (int k = 0; k < KK; k++) {
            const int off = k * CELLS + cell;        // coalesced loads
            const float h  = height[off];
            const float w  = width[off];
            const float sh = axis ? y[off] : x[off];
            c[k] = cloc + sh;                        // spot center on this axis
            const float w2    = w * w;
            const float invw2 = __fdividef(1.0f, w2);
            s2[k] = 0.72134752044f * invw2;          // log2e / (2 w^2)
            lp2[k] = axis ? 0.0f
                          : __log2f(h * 0.15915494309f * invw2);
        }

        if (axis == 0) {
            // ex: two step-4 recurrence runs; run starts at row r0 = 2hf+run.
            float2* trow = tab + lc * STRIDE + (hf << 3);   // positions 8hf..
#pragma unroll
            for (int run = 0; run < 2; run++) {
                const float r0 = (float)(2 * hf + run);
                float a[KK], dl[KK], e2s[KK];
#pragma unroll
                for (int k = 0; k < KK; k++) {
                    const float dc = r0 - c[k];
                    a[k]   = fmaf(-dc, dc * s2[k], lp2[k]);       // a(r0)
                    dl[k]  = -(fmaf(8.0f, dc, 16.0f)) * s2[k];    // a(r0+4)-a(r0)
                    e2s[k] = 32.0f * s2[k];                        // -(2nd diff)
                }
#pragma unroll
                for (int m = 0; m < 4; m += 2) {
                    const float e00 = ex2(a[0]);
                    const float e01 = ex2(a[1]);
                    a[0] += dl[0]; dl[0] -= e2s[0];
                    a[1] += dl[1]; dl[1] -= e2s[1];
                    const float e10 = ex2(a[0]);
                    const float e11 = ex2(a[1]);
                    a[0] += dl[0]; dl[0] -= e2s[0];
                    a[1] += dl[1]; dl[1] -= e2s[1];
                    *reinterpret_cast<float4*>(trow + run * 4 + m)
                        = make_float4(e00, e01, e10, e11);   // conflict-free STS.128
                }
            }
        } else {
            // ey: linear step-1 recurrence, 8 entries from d0 = 8hf.
            const float d0 = (float)(hf << 3);
            float a[KK], dl[KK], e2s[KK];
#pragma unroll
            for (int k = 0; k < KK; k++) {
                const float dc = d0 - c[k];
                a[k]   = fmaf(-dc, dc * s2[k], 0.0f);         // a(d0)
                dl[k]  = -(dc + dc + 1.0f) * s2[k];           // a(d0+1)-a(d0)
                e2s[k] = s2[k] + s2[k];                       // -(2nd diff)
            }
            float2* trow = tab + lc * STRIDE + 16 + (hf << 3);
#pragma unroll
            for (int dd = 0; dd < 8; dd += 2) {
                const float e00 = ex2(a[0]);
                const float e01 = ex2(a[1]);
                a[0] += dl[0]; dl[0] -= e2s[0];
                a[1] += dl[1]; dl[1] -= e2s[1];
                const float e10 = ex2(a[0]);
                const float e11 = ex2(a[1]);
                a[0] += dl[0]; dl[0] -= e2s[0];
                a[1] += dl[1]; dl[1] -= e2s[1];
                if ((hf << 3) + dd < DD)   // masks rows 14,15
                    *reinterpret_cast<float4*>(trow + dd)
                        = make_float4(e00, e01, e10, e11);   // conflict-free STS.128
            }
        }
    }
    __syncthreads();

    // ---------------- Phase 2: emit pixels (4 warps x 8 cells each) --------
    const int warp = t >> 5;
    const int lane = t & 31;

    const int  ls = (lane < 28) ? lane : 0;  // clamped lanes duplicate lane 0
    const int  ri = ls / 7;                  // row-subgroup 0..3
    const int  jp = ls - ri * 7;             // pair column 0..6
    const bool last_ok = ri < 2;             // r=3 rows 12,13 valid; 14,15 not

#pragma unroll
    for (int cc = 0; cc < 8; cc++) {
        const int lc = warp * 8 + cc;
        const float2* cex = tab + lc * STRIDE;   // transposed ex (pref folded)
        const float2* cey = cex + 16;            // linear ey

        // Entire ex working set: positions 4ri..4ri+3 (32B, two LDS.128).
        // exA = {r0:(s0,s1), r1:(s0,s1)}, exB = {r2:(s0,s1), r3:(s0,s1)}
        const float4 exA = *reinterpret_cast<const float4*>(cex + 4 * ri);
        const float4 exB = *reinterpret_cast<const float4*>(cex + 4 * ri + 2);
        // Round-invariant ey: one LDS.128.
        const float4 eyq = *reinterpret_cast<const float4*>(cey + 2 * jp);
        const float  bg  = bgs[lc];
        float* outp = out + (size_t)(blockbase + lc) * PIX + 2 * jp;

#pragma unroll
        for (int r = 0; r < 4; r++) {
            // compile-time component selection under full unroll (no selects)
            const float ex0 = (r == 0) ? exA.x : (r == 1) ? exA.z
                           : (r == 2) ? exB.x : exB.z;
            const float ex1 = (r == 0) ? exA.y : (r == 1) ? exA.w
                           : (r == 2) ? exB.y : exB.w;
            float v0 = fmaf(ex1, eyq.y, bg);
            v0       = fmaf(ex0, eyq.x, v0);
            float v1 = fmaf(ex1, eyq.w, bg);
            v1       = fmaf(ex0, eyq.z, v1);
            const int row = 4 * r + ri;           // garbage rows 14,15 masked
            if (r < 3 || last_ok)                 // compile-time true for r<3
                __stcs(reinterpret_cast<float2*>(outp + row * DD),
                       make_float2(v0, v1));      // streaming STG.64
        }
    }
}

extern "C" void kernel_launch(void* const* d_in, const int* in_sizes, int n_in,
                              void* d_out, int out_size)
{
    const float* height      = (const float*)d_in[0];
    const float* width       = (const float*)d_in[1];
    const float* x           = (const float*)d_in[2];
    const float* y           = (const float*)d_in[3];
    const float* background  = (const float*)d_in[4];
    const float* target_locs = (const float*)d_in[5];
    const int*   n_idx       = (const int*)d_in[6];
    const int*   f_arr       = (const int*)d_in[7];
    float*       out         = (float*)d_out;

    const int blocks = CELLS / CPB;   // 8192
    gaussian_spot_kernel<<<blocks, THREADS>>>(height, width, x, y, background,
                                              target_locs, n_idx, f_arr, out);
}